// round 1
// baseline (speedup 1.0000x reference)
#include <cuda_runtime.h>

#define BSZ    8
#define CH     512
#define NPOS   64
#define HEADS  8
#define PLANE  4096            // NR*NC
#define XSTRIDE (CH*PLANE)     // per-batch stride in x
#define NLAYER 3
#define CC     (CH*CH)         // 262144
#define SCALE  0.04419417382415922f   // 1/sqrt(512)

// scratch for K/Q/V projections (allocation-free __device__ globals)
__device__ float g_K[BSZ * XSTRIDE];
__device__ float g_Q[BSZ * XSTRIDE];
__device__ float g_V[BSZ * XSTRIDE];

// ---------------------------------------------------------------------------
// Projection GEMM: Y[bs][o][p] = sum_c W[o][c] * X[bs][c][p] + b[o]
// M=512 (o), N=4096 (p) per batch, K=512. Tiles 64x64x16, 256 thr, 4x4/thread.
// grid = (64, 8, BSZ*3); z%3 selects K/Q/V.
// ---------------------------------------------------------------------------
__global__ __launch_bounds__(256) void proj_kernel(
    const float* __restrict__ x,
    const float* __restrict__ Wk, const float* __restrict__ bk,
    const float* __restrict__ Wq, const float* __restrict__ bq,
    const float* __restrict__ Wv, const float* __restrict__ bv)
{
    const int bs    = blockIdx.z / 3;
    const int which = blockIdx.z % 3;
    const float* W; const float* b; float* Y;
    if (which == 0)      { W = Wk; b = bk; Y = g_K; }
    else if (which == 1) { W = Wq; b = bq; Y = g_Q; }
    else                 { W = Wv; b = bv; Y = g_V; }
    const float* X = x + (size_t)bs * XSTRIDE;
    Y += (size_t)bs * XSTRIDE;

    const int p0 = blockIdx.x * 64;
    const int o0 = blockIdx.y * 64;

    __shared__ float Ws[16][64];   // [k][o]
    __shared__ float Xs[16][64];   // [k][p]

    const int tid = threadIdx.x;
    const int tx  = tid & 15;
    const int ty  = tid >> 4;

    float acc[4][4] = {};

    for (int c0 = 0; c0 < CH; c0 += 16) {
        // load W tile: thread -> (oo = tid/4, kk4 = (tid%4)*4), float4 along c
        {
            const int oo  = tid >> 2;
            const int kk4 = (tid & 3) * 4;
            const float4 wv = *(const float4*)(W + (size_t)(o0 + oo) * CH + c0 + kk4);
            Ws[kk4 + 0][oo] = wv.x;
            Ws[kk4 + 1][oo] = wv.y;
            Ws[kk4 + 2][oo] = wv.z;
            Ws[kk4 + 3][oo] = wv.w;
        }
        // load X tile: 4 rows of 64, 4 passes
        {
            const int kk = tid >> 6;   // 0..3
            const int pp = tid & 63;
            #pragma unroll
            for (int r = 0; r < 4; r++)
                Xs[kk + r * 4][pp] = X[(size_t)(c0 + kk + r * 4) * PLANE + p0 + pp];
        }
        __syncthreads();

        #pragma unroll
        for (int k = 0; k < 16; k++) {
            const float4 a  = *(const float4*)&Ws[k][ty * 4];
            const float4 xv = *(const float4*)&Xs[k][tx * 4];
            acc[0][0] += a.x * xv.x; acc[0][1] += a.x * xv.y; acc[0][2] += a.x * xv.z; acc[0][3] += a.x * xv.w;
            acc[1][0] += a.y * xv.x; acc[1][1] += a.y * xv.y; acc[1][2] += a.y * xv.z; acc[1][3] += a.y * xv.w;
            acc[2][0] += a.z * xv.x; acc[2][1] += a.z * xv.y; acc[2][2] += a.z * xv.z; acc[2][3] += a.z * xv.w;
            acc[3][0] += a.w * xv.x; acc[3][1] += a.w * xv.y; acc[3][2] += a.w * xv.z; acc[3][3] += a.w * xv.w;
        }
        __syncthreads();
    }

    #pragma unroll
    for (int ii = 0; ii < 4; ii++) {
        const int o = o0 + ty * 4 + ii;
        const float bb = b[o];
        float4 o4;
        o4.x = acc[ii][0] + bb;
        o4.y = acc[ii][1] + bb;
        o4.z = acc[ii][2] + bb;
        o4.w = acc[ii][3] + bb;
        *(float4*)(Y + (size_t)o * PLANE + p0 + tx * 4) = o4;
    }
}

// ---------------------------------------------------------------------------
// Fused attention for one (group, head):
//   logits[k][q] = scale * sum_d K[d][k] Q[d][q]  (- mask penalty on keys)
//   P = softmax over k; O[d][q] = sum_k V[d][k] P[k][q]; x += O (residual)
// Column attn: pstride=1, base = bs*XSTRIDE + r*64 (r = row index)
// Row attn:    pstride=64, base = bs*XSTRIDE + r    (r = col index)
// grid = (512, 8), 256 threads. smem = 3 * 16KB = 48KB exactly.
// ---------------------------------------------------------------------------
__global__ __launch_bounds__(256) void attn_kernel(
    float* __restrict__ x, const float* __restrict__ masks, int isRow)
{
    __shared__ float Ks[64][64];
    __shared__ float Qs[64][64];   // reused to hold logits / softmax P
    __shared__ float Vs[64][64];

    const int g  = blockIdx.x;      // 0..511 (bs, r)
    const int h  = blockIdx.y;      // head
    const int bs = g >> 6;
    const int r  = g & 63;
    const int pstride = isRow ? 64 : 1;
    const size_t base = (size_t)bs * XSTRIDE + (isRow ? r : r * 64);
    const float* mb   = masks + (size_t)bs * PLANE + (isRow ? r : r * 64);

    const int tid = threadIdx.x;
    const int n   = tid & 63;
    const int dq  = tid >> 6;       // 0..3

    // load K/Q/V head tiles: channel c = d*8 + h, position n with stride
    #pragma unroll 4
    for (int pass = 0; pass < 16; pass++) {
        const int d = dq + pass * 4;
        const size_t a = base + (size_t)(d * HEADS + h) * PLANE + (size_t)n * pstride;
        Ks[d][n] = g_K[a];
        Qs[d][n] = g_Q[a];
        Vs[d][n] = g_V[a];
    }
    __syncthreads();

    const int tx = tid & 15;
    const int ty = tid >> 4;

    // logits tile in registers: rows k = 4*ty.., cols q = 4*tx..
    float acc[4][4] = {};
    #pragma unroll 8
    for (int d = 0; d < 64; d++) {
        const float4 a  = *(const float4*)&Ks[d][ty * 4];
        const float4 qv = *(const float4*)&Qs[d][tx * 4];
        acc[0][0] += a.x * qv.x; acc[0][1] += a.x * qv.y; acc[0][2] += a.x * qv.z; acc[0][3] += a.x * qv.w;
        acc[1][0] += a.y * qv.x; acc[1][1] += a.y * qv.y; acc[1][2] += a.y * qv.z; acc[1][3] += a.y * qv.w;
        acc[2][0] += a.z * qv.x; acc[2][1] += a.z * qv.y; acc[2][2] += a.z * qv.z; acc[2][3] += a.z * qv.w;
        acc[3][0] += a.w * qv.x; acc[3][1] += a.w * qv.y; acc[3][2] += a.w * qv.z; acc[3][3] += a.w * qv.w;
    }

    // mask penalty for this thread's 4 key rows
    float mk[4];
    #pragma unroll
    for (int ii = 0; ii < 4; ii++)
        mk[ii] = (1.0f - mb[(size_t)(ty * 4 + ii) * pstride]) * 1e8f;

    __syncthreads();   // all threads done reading Qs (q-tile)

    #pragma unroll
    for (int ii = 0; ii < 4; ii++) {
        float4 o4;
        o4.x = acc[ii][0] * SCALE - mk[ii];
        o4.y = acc[ii][1] * SCALE - mk[ii];
        o4.z = acc[ii][2] * SCALE - mk[ii];
        o4.w = acc[ii][3] * SCALE - mk[ii];
        *(float4*)&Qs[ty * 4 + ii][tx * 4] = o4;   // Qs now = logits[k][q]
    }
    __syncthreads();

    // softmax over keys k, one thread per query column (banks conflict-free)
    if (tid < 64) {
        float m = -1e30f;
        #pragma unroll 8
        for (int k = 0; k < 64; k++) m = fmaxf(m, Qs[k][tid]);
        float s = 0.0f;
        #pragma unroll 8
        for (int k = 0; k < 64; k++) {
            const float e = __expf(Qs[k][tid] - m);
            Qs[k][tid] = e;
            s += e;
        }
        const float inv = 1.0f / s;
        #pragma unroll 8
        for (int k = 0; k < 64; k++) Qs[k][tid] *= inv;
    }
    __syncthreads();

    // O[d][q] = sum_k V[d][k] * P[k][q]
    float oacc[4][4] = {};
    #pragma unroll 8
    for (int k = 0; k < 64; k++) {
        const float4 p = *(const float4*)&Qs[k][tx * 4];
        const float v0 = Vs[ty * 4 + 0][k];
        const float v1 = Vs[ty * 4 + 1][k];
        const float v2 = Vs[ty * 4 + 2][k];
        const float v3 = Vs[ty * 4 + 3][k];
        oacc[0][0] += v0 * p.x; oacc[0][1] += v0 * p.y; oacc[0][2] += v0 * p.z; oacc[0][3] += v0 * p.w;
        oacc[1][0] += v1 * p.x; oacc[1][1] += v1 * p.y; oacc[1][2] += v1 * p.z; oacc[1][3] += v1 * p.w;
        oacc[2][0] += v2 * p.x; oacc[2][1] += v2 * p.y; oacc[2][2] += v2 * p.z; oacc[2][3] += v2 * p.w;
        oacc[3][0] += v3 * p.x; oacc[3][1] += v3 * p.y; oacc[3][2] += v3 * p.z; oacc[3][3] += v3 * p.w;
    }

    // residual: x += O (blocks touch disjoint (channel, position) sets)
    #pragma unroll
    for (int ii = 0; ii < 4; ii++) {
        const int d = ty * 4 + ii;
        const size_t rowa = base + (size_t)(d * HEADS + h) * PLANE;
        #pragma unroll
        for (int jj = 0; jj < 4; jj++) {
            const int q = tx * 4 + jj;
            const size_t a = rowa + (size_t)q * pstride;
            x[a] += oacc[ii][jj];
        }
    }
}

// ---------------------------------------------------------------------------
extern "C" void kernel_launch(void* const* d_in, const int* in_sizes, int n_in,
                              void* d_out, int out_size)
{
    const float* feat  = (const float*)d_in[0];
    const float* masks = (const float*)d_in[1];

    // Detect input ordering:
    //   signature order: feat, masks, cWk, cbk, cWq, cbq, cWv, cbv, rWk, rbk, ...
    //   dict order:      feat, masks, cWk, cWq, cWv, rWk, rWq, rWv, cbk, cbq, cbv, rbk, rbq, rbv
    const float *cWk, *cbk, *cWq, *cbq, *cWv, *cbv;
    const float *rWk, *rbk, *rWq, *rbq, *rWv, *rbv;
    if (n_in >= 4 && in_sizes[3] == NLAYER * CH) {
        // signature (bias interleaved) order
        cWk = (const float*)d_in[2];  cbk = (const float*)d_in[3];
        cWq = (const float*)d_in[4];  cbq = (const float*)d_in[5];
        cWv = (const float*)d_in[6];  cbv = (const float*)d_in[7];
        rWk = (const float*)d_in[8];  rbk = (const float*)d_in[9];
        rWq = (const float*)d_in[10]; rbq = (const float*)d_in[11];
        rWv = (const float*)d_in[12]; rbv = (const float*)d_in[13];
    } else {
        // dict insertion order
        cWk = (const float*)d_in[2];  cWq = (const float*)d_in[3];
        cWv = (const float*)d_in[4];
        rWk = (const float*)d_in[5];  rWq = (const float*)d_in[6];
        rWv = (const float*)d_in[7];
        cbk = (const float*)d_in[8];  cbq = (const float*)d_in[9];
        cbv = (const float*)d_in[10];
        rbk = (const float*)d_in[11]; rbq = (const float*)d_in[12];
        rbv = (const float*)d_in[13];
    }

    float* xbuf = (float*)d_out;   // d_out's x region doubles as working buffer
    const size_t xElems = (size_t)BSZ * XSTRIDE;

    cudaMemcpyAsync(xbuf, feat, xElems * sizeof(float), cudaMemcpyDeviceToDevice);

    const dim3 pgrid(PLANE / 64, CH / 64, BSZ * 3);
    const dim3 agrid(BSZ * NPOS, HEADS);

    for (int i = 0; i < NLAYER; i++) {
        // column attention (positions = nc, stride 1)
        proj_kernel<<<pgrid, 256>>>(xbuf,
            cWk + (size_t)i * CC, cbk + (size_t)i * CH,
            cWq + (size_t)i * CC, cbq + (size_t)i * CH,
            cWv + (size_t)i * CC, cbv + (size_t)i * CH);
        attn_kernel<<<agrid, 256>>>(xbuf, masks, 0);
        // row attention (positions = nr, stride 64)
        proj_kernel<<<pgrid, 256>>>(xbuf,
            rWk + (size_t)i * CC, rbk + (size_t)i * CH,
            rWq + (size_t)i * CC, rbq + (size_t)i * CH,
            rWv + (size_t)i * CC, rbv + (size_t)i * CH);
        attn_kernel<<<agrid, 256>>>(xbuf, masks, 1);
    }

    // second output of the tuple: masks passthrough
    if ((size_t)out_size > xElems) {
        const size_t mElems = (size_t)out_size - xElems;
        cudaMemcpyAsync((float*)d_out + xElems, masks, mElems * sizeof(float),
                        cudaMemcpyDeviceToDevice);
    }
}

// round 8
// speedup vs baseline: 1.7721x; 1.7721x over previous
#include <cuda_runtime.h>
#include <cuda_bf16.h>
#include <cstdint>

#define BSZ    8
#define CH     512
#define NPOS   64
#define HEADS  8
#define PLANE  4096
#define XSTRIDE (CH*PLANE)
#define NLAYER 3
#define CC     (CH*CH)
#define SCALE  0.04419417382415922f

// fp32 K/Q/V in [bs][o][p] layout (attn kernel reads these)
__device__ float g_K[BSZ * XSTRIDE];
__device__ float g_Q[BSZ * XSTRIDE];
__device__ float g_V[BSZ * XSTRIDE];

// ---------------------------------------------------------------------------
// smem geometry for proj GEMM (bf16 elems), double buffered
// ---------------------------------------------------------------------------
#define LDA 40            // 32 + 8 pad  (A rows: 80B -> conflict-free ldmatrix)
#define LDB 136           // 128 + 8 pad (B rows: 272B -> conflict-free ldmatrix)
#define A_ELE (128*LDA)   // 5120
#define B_ELE (32*LDB)    // 4352
#define STAGE_ELEMS (2*A_ELE + 2*B_ELE)   // Ah, Al, Bh, Bl = 18944
#define PROJ_SMEM (2 * STAGE_ELEMS * 2)   // bytes = 75776

__device__ __forceinline__ uint32_t smem_u32(const void* p) {
    uint32_t a;
    asm("{ .reg .u64 t; cvta.to.shared.u64 t, %1; cvt.u32.u64 %0, t; }" : "=r"(a) : "l"(p));
    return a;
}

#define LDMX4(r, addr) asm volatile( \
    "ldmatrix.sync.aligned.m8n8.x4.shared.b16 {%0,%1,%2,%3}, [%4];" \
    : "=r"((r)[0]), "=r"((r)[1]), "=r"((r)[2]), "=r"((r)[3]) : "r"(addr))
#define LDMX4T(r, addr) asm volatile( \
    "ldmatrix.sync.aligned.m8n8.x4.trans.shared.b16 {%0,%1,%2,%3}, [%4];" \
    : "=r"((r)[0]), "=r"((r)[1]), "=r"((r)[2]), "=r"((r)[3]) : "r"(addr))
#define MMA16816(c, a, b) asm volatile( \
    "mma.sync.aligned.m16n8k16.row.col.f32.bf16.bf16.f32 " \
    "{%0,%1,%2,%3}, {%4,%5,%6,%7}, {%8,%9}, {%0,%1,%2,%3};" \
    : "+f"((c)[0]), "+f"((c)[1]), "+f"((c)[2]), "+f"((c)[3]) \
    : "r"((a)[0]), "r"((a)[1]), "r"((a)[2]), "r"((a)[3]), "r"((b)[0]), "r"((b)[1]))

__device__ __forceinline__ void split2(float x, float y, uint32_t& hi, uint32_t& lo) {
    __nv_bfloat162 h = __floats2bfloat162_rn(x, y);
    float rx = x - __bfloat162float(h.x);
    float ry = y - __bfloat162float(h.y);
    __nv_bfloat162 l = __floats2bfloat162_rn(rx, ry);
    hi = *reinterpret_cast<uint32_t*>(&h);
    lo = *reinterpret_cast<uint32_t*>(&l);
}

// ---------------------------------------------------------------------------
// Projection GEMM via mma.sync (HMMA), bf16x3 split, fp32 accum.
// Y[bs][o][p] = sum_c W[o][c] * X[bs][c][p] + b[o]
// grid = (32 ptiles, 4 otiles, BSZ*3); 256 threads (8 warps, 2x4).
// ---------------------------------------------------------------------------
__global__ __launch_bounds__(256, 1) void proj_mma_kernel(
    const float* __restrict__ x,
    const float* __restrict__ Wk, const float* __restrict__ bk,
    const float* __restrict__ Wq, const float* __restrict__ bq,
    const float* __restrict__ Wv, const float* __restrict__ bv)
{
    extern __shared__ __nv_bfloat16 sh[];
    const uint32_t shb = smem_u32(sh);

    const int bs    = blockIdx.z / 3;
    const int which = blockIdx.z % 3;
    const float* W; const float* bvec; float* Y;
    if (which == 0)      { W = Wk; bvec = bk; Y = g_K; }
    else if (which == 1) { W = Wq; bvec = bq; Y = g_Q; }
    else                 { W = Wv; bvec = bv; Y = g_V; }
    const float* X = x + (size_t)bs * XSTRIDE;
    Y += (size_t)bs * XSTRIDE;

    const int p0 = blockIdx.x * 128;
    const int o0 = blockIdx.y * 128;

    const int tid  = threadIdx.x;
    const int lane = tid & 31;
    const int warp = tid >> 5;
    const int wm   = warp & 1;        // 0..1  -> m offset wm*64
    const int wn   = warp >> 1;       // 0..3  -> n offset wn*32

    // staging assignments
    const int arow = tid >> 1;              // 0..127
    const int acg  = (tid & 1) * 16;        // col group (16 cols)
    const int brow = tid >> 3;              // 0..31
    const int bcg  = (tid & 7) * 16;

    float acc[4][4][4];
    #pragma unroll
    for (int i = 0; i < 4; i++)
        #pragma unroll
        for (int j = 0; j < 4; j++)
            #pragma unroll
            for (int k = 0; k < 4; k++) acc[i][j][k] = 0.0f;

    float4 va[4], vb[4];

    // ---- prologue: load + store stage 0
    #pragma unroll
    for (int i = 0; i < 4; i++) {
        va[i] = *(const float4*)(W + (size_t)(o0 + arow) * CH + acg + i * 4);
        vb[i] = *(const float4*)(X + (size_t)brow * PLANE + p0 + bcg + i * 4);
    }
    {
        __nv_bfloat16* Ah = sh;             __nv_bfloat16* Al = sh + A_ELE;
        __nv_bfloat16* Bh = sh + 2*A_ELE;   __nv_bfloat16* Bl = sh + 2*A_ELE + B_ELE;
        #pragma unroll
        for (int i = 0; i < 4; i++) {
            uint32_t h0, l0, h1, l1;
            split2(va[i].x, va[i].y, h0, l0);
            split2(va[i].z, va[i].w, h1, l1);
            int idx = arow * LDA + acg + i * 4;
            *(uint32_t*)(Ah + idx) = h0; *(uint32_t*)(Ah + idx + 2) = h1;
            *(uint32_t*)(Al + idx) = l0; *(uint32_t*)(Al + idx + 2) = l1;
            split2(vb[i].x, vb[i].y, h0, l0);
            split2(vb[i].z, vb[i].w, h1, l1);
            idx = brow * LDB + bcg + i * 4;
            *(uint32_t*)(Bh + idx) = h0; *(uint32_t*)(Bh + idx + 2) = h1;
            *(uint32_t*)(Bl + idx) = l0; *(uint32_t*)(Bl + idx + 2) = l1;
        }
    }
    __syncthreads();

    for (int ks = 0; ks < 16; ks++) {
        const int s = ks & 1;

        // issue gmem loads for next stage early
        if (ks < 15) {
            const int c0 = (ks + 1) * 32;
            #pragma unroll
            for (int i = 0; i < 4; i++) {
                va[i] = *(const float4*)(W + (size_t)(o0 + arow) * CH + c0 + acg + i * 4);
                vb[i] = *(const float4*)(X + (size_t)(c0 + brow) * PLANE + p0 + bcg + i * 4);
            }
        }

        // compute on stage s
        const uint32_t ah_b = shb + (uint32_t)(s * STAGE_ELEMS) * 2;
        const uint32_t al_b = ah_b + A_ELE * 2;
        const uint32_t bh_b = ah_b + 2 * A_ELE * 2;
        const uint32_t bl_b = bh_b + B_ELE * 2;

        #pragma unroll
        for (int k16 = 0; k16 < 2; k16++) {
            const int k0 = k16 * 16;
            uint32_t bh[8], bl[8];
            #pragma unroll
            for (int half = 0; half < 2; half++) {
                const uint32_t boff =
                    (uint32_t)((k0 + (lane & 15)) * LDB + wn * 32 + half * 16 + ((lane >> 4) << 3)) * 2;
                LDMX4T(bh + half * 4, bh_b + boff);
                LDMX4T(bl + half * 4, bl_b + boff);
            }
            #pragma unroll
            for (int mi = 0; mi < 4; mi++) {
                uint32_t ah[4], al[4];
                const uint32_t aoff =
                    (uint32_t)((wm * 64 + mi * 16 + (lane & 15)) * LDA + k0 + ((lane >> 4) << 3)) * 2;
                LDMX4(ah, ah_b + aoff);
                LDMX4(al, al_b + aoff);
                #pragma unroll
                for (int ni = 0; ni < 4; ni++) {
                    MMA16816(acc[mi][ni], ah, &bh[ni * 2]);
                    MMA16816(acc[mi][ni], ah, &bl[ni * 2]);
                    MMA16816(acc[mi][ni], al, &bh[ni * 2]);
                }
            }
        }

        // store next stage into the other buffer
        if (ks < 15) {
            const int ns = 1 - s;
            __nv_bfloat16* Ah = sh + ns * STAGE_ELEMS;
            __nv_bfloat16* Al = Ah + A_ELE;
            __nv_bfloat16* Bh = Ah + 2 * A_ELE;
            __nv_bfloat16* Bl = Bh + B_ELE;
            #pragma unroll
            for (int i = 0; i < 4; i++) {
                uint32_t h0, l0, h1, l1;
                split2(va[i].x, va[i].y, h0, l0);
                split2(va[i].z, va[i].w, h1, l1);
                int idx = arow * LDA + acg + i * 4;
                *(uint32_t*)(Ah + idx) = h0; *(uint32_t*)(Ah + idx + 2) = h1;
                *(uint32_t*)(Al + idx) = l0; *(uint32_t*)(Al + idx + 2) = l1;
                split2(vb[i].x, vb[i].y, h0, l0);
                split2(vb[i].z, vb[i].w, h1, l1);
                idx = brow * LDB + bcg + i * 4;
                *(uint32_t*)(Bh + idx) = h0; *(uint32_t*)(Bh + idx + 2) = h1;
                *(uint32_t*)(Bl + idx) = l0; *(uint32_t*)(Bl + idx + 2) = l1;
            }
        }
        __syncthreads();
    }

    // ---- epilogue: bias + store fp32, [o][p]
    #pragma unroll
    for (int mi = 0; mi < 4; mi++) {
        const int mbase = o0 + wm * 64 + mi * 16;
        const int r = lane >> 2;
        const float bA = __ldg(&bvec[mbase + r]);
        const float bB = __ldg(&bvec[mbase + 8 + r]);
        #pragma unroll
        for (int ni = 0; ni < 4; ni++) {
            const int n = p0 + wn * 32 + ni * 8 + (lane & 3) * 2;
            float2 v0 = { acc[mi][ni][0] + bA, acc[mi][ni][1] + bA };
            float2 v1 = { acc[mi][ni][2] + bB, acc[mi][ni][3] + bB };
            *(float2*)(Y + (size_t)(mbase + r) * PLANE + n)     = v0;
            *(float2*)(Y + (size_t)(mbase + 8 + r) * PLANE + n) = v1;
        }
    }
}

// ---------------------------------------------------------------------------
// Fused attention (unchanged from passing R1 kernel)
// ---------------------------------------------------------------------------
__global__ __launch_bounds__(256) void attn_kernel(
    float* __restrict__ x, const float* __restrict__ masks, int isRow)
{
    __shared__ float Ks[64][64];
    __shared__ float Qs[64][64];
    __shared__ float Vs[64][64];

    const int g  = blockIdx.x;
    const int h  = blockIdx.y;
    const int bs = g >> 6;
    const int r  = g & 63;
    const int pstride = isRow ? 64 : 1;
    const size_t base = (size_t)bs * XSTRIDE + (isRow ? r : r * 64);
    const float* mb   = masks + (size_t)bs * PLANE + (isRow ? r : r * 64);

    const int tid = threadIdx.x;
    const int n   = tid & 63;
    const int dq  = tid >> 6;

    #pragma unroll 4
    for (int pass = 0; pass < 16; pass++) {
        const int d = dq + pass * 4;
        const size_t a = base + (size_t)(d * HEADS + h) * PLANE + (size_t)n * pstride;
        Ks[d][n] = g_K[a];
        Qs[d][n] = g_Q[a];
        Vs[d][n] = g_V[a];
    }
    __syncthreads();

    const int tx = tid & 15;
    const int ty = tid >> 4;

    float acc[4][4] = {};
    #pragma unroll 8
    for (int d = 0; d < 64; d++) {
        const float4 a  = *(const float4*)&Ks[d][ty * 4];
        const float4 qv = *(const float4*)&Qs[d][tx * 4];
        acc[0][0] += a.x * qv.x; acc[0][1] += a.x * qv.y; acc[0][2] += a.x * qv.z; acc[0][3] += a.x * qv.w;
        acc[1][0] += a.y * qv.x; acc[1][1] += a.y * qv.y; acc[1][2] += a.y * qv.z; acc[1][3] += a.y * qv.w;
        acc[2][0] += a.z * qv.x; acc[2][1] += a.z * qv.y; acc[2][2] += a.z * qv.z; acc[2][3] += a.z * qv.w;
        acc[3][0] += a.w * qv.x; acc[3][1] += a.w * qv.y; acc[3][2] += a.w * qv.z; acc[3][3] += a.w * qv.w;
    }

    float mk[4];
    #pragma unroll
    for (int ii = 0; ii < 4; ii++)
        mk[ii] = (1.0f - mb[(size_t)(ty * 4 + ii) * pstride]) * 1e8f;

    __syncthreads();

    #pragma unroll
    for (int ii = 0; ii < 4; ii++) {
        float4 o4;
        o4.x = acc[ii][0] * SCALE - mk[ii];
        o4.y = acc[ii][1] * SCALE - mk[ii];
        o4.z = acc[ii][2] * SCALE - mk[ii];
        o4.w = acc[ii][3] * SCALE - mk[ii];
        *(float4*)&Qs[ty * 4 + ii][tx * 4] = o4;
    }
    __syncthreads();

    if (tid < 64) {
        float m = -1e30f;
        #pragma unroll 8
        for (int k = 0; k < 64; k++) m = fmaxf(m, Qs[k][tid]);
        float s = 0.0f;
        #pragma unroll 8
        for (int k = 0; k < 64; k++) {
            const float e = __expf(Qs[k][tid] - m);
            Qs[k][tid] = e;
            s += e;
        }
        const float inv = 1.0f / s;
        #pragma unroll 8
        for (int k = 0; k < 64; k++) Qs[k][tid] *= inv;
    }
    __syncthreads();

    float oacc[4][4] = {};
    #pragma unroll 8
    for (int k = 0; k < 64; k++) {
        const float4 p = *(const float4*)&Qs[k][tx * 4];
        const float v0 = Vs[ty * 4 + 0][k];
        const float v1 = Vs[ty * 4 + 1][k];
        const float v2 = Vs[ty * 4 + 2][k];
        const float v3 = Vs[ty * 4 + 3][k];
        oacc[0][0] += v0 * p.x; oacc[0][1] += v0 * p.y; oacc[0][2] += v0 * p.z; oacc[0][3] += v0 * p.w;
        oacc[1][0] += v1 * p.x; oacc[1][1] += v1 * p.y; oacc[1][2] += v1 * p.z; oacc[1][3] += v1 * p.w;
        oacc[2][0] += v2 * p.x; oacc[2][1] += v2 * p.y; oacc[2][2] += v2 * p.z; oacc[2][3] += v2 * p.w;
        oacc[3][0] += v3 * p.x; oacc[3][1] += v3 * p.y; oacc[3][2] += v3 * p.z; oacc[3][3] += v3 * p.w;
    }

    #pragma unroll
    for (int ii = 0; ii < 4; ii++) {
        const int d = ty * 4 + ii;
        const size_t rowa = base + (size_t)(d * HEADS + h) * PLANE;
        #pragma unroll
        for (int jj = 0; jj < 4; jj++) {
            const int q = tx * 4 + jj;
            const size_t a = rowa + (size_t)q * pstride;
            x[a] += oacc[ii][jj];
        }
    }
}

// ---------------------------------------------------------------------------
extern "C" void kernel_launch(void* const* d_in, const int* in_sizes, int n_in,
                              void* d_out, int out_size)
{
    const float* feat  = (const float*)d_in[0];
    const float* masks = (const float*)d_in[1];

    const float *cWk, *cbk, *cWq, *cbq, *cWv, *cbv;
    const float *rWk, *rbk, *rWq, *rbq, *rWv, *rbv;
    if (n_in >= 4 && in_sizes[3] == NLAYER * CH) {
        cWk = (const float*)d_in[2];  cbk = (const float*)d_in[3];
        cWq = (const float*)d_in[4];  cbq = (const float*)d_in[5];
        cWv = (const float*)d_in[6];  cbv = (const float*)d_in[7];
        rWk = (const float*)d_in[8];  rbk = (const float*)d_in[9];
        rWq = (const float*)d_in[10]; rbq = (const float*)d_in[11];
        rWv = (const float*)d_in[12]; rbv = (const float*)d_in[13];
    } else {
        cWk = (const float*)d_in[2];  cWq = (const float*)d_in[3];
        cWv = (const float*)d_in[4];
        rWk = (const float*)d_in[5];  rWq = (const float*)d_in[6];
        rWv = (const float*)d_in[7];
        cbk = (const float*)d_in[8];  cbq = (const float*)d_in[9];
        cbv = (const float*)d_in[10];
        rbk = (const float*)d_in[11]; rbq = (const float*)d_in[12];
        rbv = (const float*)d_in[13];
    }

    cudaFuncSetAttribute(proj_mma_kernel,
        cudaFuncAttributeMaxDynamicSharedMemorySize, PROJ_SMEM);

    float* xbuf = (float*)d_out;
    const size_t xElems = (size_t)BSZ * XSTRIDE;

    cudaMemcpyAsync(xbuf, feat, xElems * sizeof(float), cudaMemcpyDeviceToDevice);

    const dim3 pgrid(PLANE / 128, CH / 128, BSZ * 3);
    const dim3 agrid(BSZ * NPOS, HEADS);

    for (int i = 0; i < NLAYER; i++) {
        // column attention (positions = nc, stride 1)
        proj_mma_kernel<<<pgrid, 256, PROJ_SMEM>>>(xbuf,
            cWk + (size_t)i * CC, cbk + (size_t)i * CH,
            cWq + (size_t)i * CC, cbq + (size_t)i * CH,
            cWv + (size_t)i * CC, cbv + (size_t)i * CH);
        attn_kernel<<<agrid, 256>>>(xbuf, masks, 0);
        // row attention (positions = nr, stride 64)
        proj_mma_kernel<<<pgrid, 256, PROJ_SMEM>>>(xbuf,
            rWk + (size_t)i * CC, rbk + (size_t)i * CH,
            rWq + (size_t)i * CC, rbq + (size_t)i * CH,
            rWv + (size_t)i * CC, rbv + (size_t)i * CH);
        attn_kernel<<<agrid, 256>>>(xbuf, masks, 1);
    }

    if ((size_t)out_size > xElems) {
        const size_t mElems = (size_t)out_size - xElems;
        cudaMemcpyAsync((float*)d_out + xElems, masks, mElems * sizeof(float),
                        cudaMemcpyDeviceToDevice);
    }
}